// round 11
// baseline (speedup 1.0000x reference)
#include <cuda_runtime.h>
#include <math.h>

// Problem constants: B=8, T=1024, V=10000, N=8192, K=2, E=8
#define VDIM    10000
#define NROWS   8192
#define NE      8
#define GRID    1184      // 148 SMs x 8 resident blocks -> single wave
#define MOEBLK  32        // 32 of the 6-row blocks also do MoE side losses
#define MAXROWS 7         // max rows per block (8192 = 1088*7 + 96*6)

// Scratch (no device allocation allowed -> __device__ globals)
__device__ float    g_row_partial[NROWS];
// per-moe-block partials:
// [0]=z_local [1]=z_global [2..9]=cnt_l [10..17]=cnt_g [18..25]=sum_l [26..33]=sum_g
__device__ float    g_bpart[MOEBLK][34];
__device__ unsigned g_ctr;          // zero-init; atomicInc wraps -> replay-safe

__device__ __forceinline__ float lse8(float4 a, float4 b)
{
    float m = fmaxf(fmaxf(fmaxf(a.x, a.y), fmaxf(a.z, a.w)),
                    fmaxf(fmaxf(b.x, b.y), fmaxf(b.z, b.w)));
    float s = __expf(a.x - m) + __expf(a.y - m) + __expf(a.z - m) + __expf(a.w - m)
            + __expf(b.x - m) + __expf(b.y - m) + __expf(b.z - m) + __expf(b.w - m);
    return m + __logf(s);
}

// ---------------------------------------------------------------------------
// One kernel does everything:
//   phase 1: persistent barrier-free row loop (label smoothing partials)
//   phase 2: MoE side losses in 32 of the lighter (6-row) blocks
//   phase 3: last block (threadfence reduction) assembles the scalar
// ---------------------------------------------------------------------------
__global__ __launch_bounds__(256) void fused_kernel(
    const float* __restrict__ x, const void* __restrict__ target,
    const float* __restrict__ tv_l, const void* __restrict__ ti_l, const float* __restrict__ gl_l,
    const float* __restrict__ tv_g, const void* __restrict__ ti_g, const float* __restrict__ gl_g,
    float* __restrict__ out)
{
    __shared__ float sp[MAXROWS][8][2];   // per-row per-warp (s, sx)
    __shared__ int   s_is64tgt;
    const int tid  = threadIdx.x;
    const int lane = tid & 31, warp = tid >> 5;
    const int bid  = blockIdx.x;

    // dtype detection for target: int64 non-negative small values viewed as
    // u32 have ALL odd words zero; int32 targets in [0,10000) never do.
    if (warp == 0) {
        unsigned tw = ((const unsigned*)target)[1 + 2 * lane];
        unsigned nz = __ballot_sync(0xffffffffu, tw != 0u);
        if (lane == 0) s_is64tgt = (nz == 0u);
    }

    // ---- phase 1: rows bid, bid+GRID, ... ; NO block barrier inside loop
    int nrows = 0;
    for (int row = bid, it = 0; row < NROWS; row += GRID, it++) {
        const float4* x4 = (const float4*)(x + (size_t)row * VDIM);

        float s0 = 0.f, s1 = 0.f, s2 = 0.f, s3 = 0.f;
        float a0 = 0.f, a1 = 0.f, a2 = 0.f, a3 = 0.f;

        // 2500 float4 per row = 9 full strides of 256 + tail of 196
#pragma unroll
        for (int k = 0; k < 9; k++) {
            float4 v = x4[k * 256 + tid];
            a0 += v.x; a1 += v.y; a2 += v.z; a3 += v.w;
            s0 += __expf(v.x); s1 += __expf(v.y);
            s2 += __expf(v.z); s3 += __expf(v.w);
        }
        if (tid < 196) {
            float4 v = x4[2304 + tid];
            a0 += v.x; a1 += v.y; a2 += v.z; a3 += v.w;
            s0 += __expf(v.x); s1 += __expf(v.y);
            s2 += __expf(v.z); s3 += __expf(v.w);
        }

        float s  = (s0 + s1) + (s2 + s3);
        float sx = (a0 + a1) + (a2 + a3);
#pragma unroll
        for (int off = 16; off; off >>= 1) {
            s  += __shfl_down_sync(0xffffffffu, s,  off);
            sx += __shfl_down_sync(0xffffffffu, sx, off);
        }
        if (lane == 0) { sp[it][warp][0] = s; sp[it][warp][1] = sx; }
        nrows = it + 1;
    }
    __syncthreads();   // one barrier for the whole phase

    // finalize: one thread per row
    if (tid < nrows) {
        const int row = bid + tid * GRID;
        float s = 0.f, sx = 0.f;
#pragma unroll
        for (int w = 0; w < 8; w++) { s += sp[tid][w][0]; sx += sp[tid][w][1]; }
        float lse = __logf(s);
        long long tgt = s_is64tgt ? ((const long long*)target)[row]
                                  : (long long)((const int*)target)[row];
        float kl = 0.f;
        if (tgt >= 0) {
            const float SM  = 0.1f / (float)(VDIM - 1);
            const float ENT = -1.2461070101f;  // 0.1*log(0.1/9999)+0.9*log(0.9)
            float xt = __ldg(x + (size_t)row * VDIM + tgt);
            float sum_logp = sx - (float)VDIM * lse;
            float logp_tgt = xt - lse;
            float cross = SM * sum_logp + (0.9f - SM) * logp_tgt;
            kl = ENT - cross;
        }
        g_row_partial[row] = kl;
    }

    // ---- phase 2: MoE side losses (32 of the lighter 6-row blocks)
    if (bid >= GRID - MOEBLK) {
        const int mb = bid - (GRID - MOEBLK);   // 0..31

        __shared__ float s_acc[32];  // [0..7]=cnt_l [8..15]=cnt_g [16..23]=sum_l [24..31]=sum_g
        __shared__ float s_z[8][2];
        __shared__ int   s_is64[2];

        if (tid < 32) {
            s_acc[tid] = 0.f;
            unsigned wl = ((const unsigned*)ti_l)[1 + 2 * tid];
            unsigned wg = ((const unsigned*)ti_g)[1 + 2 * tid];
            unsigned bl = __ballot_sync(0xffffffffu, wl != 0u);
            unsigned bg = __ballot_sync(0xffffffffu, wg != 0u);
            if (tid == 0) { s_is64[0] = (bl == 0u); s_is64[1] = (bg == 0u); }
        }
        __syncthreads();

        const int gid = mb * 256 + tid;          // 0..8191
        const int i64l = s_is64[0], i64g = s_is64[1];

#pragma unroll
        for (int rep = 0; rep < 2; rep++) {
            int e = gid + rep * NROWS;           // flattened (N,K) row-major
            float vl = tv_l[e];
            int il = i64l ? (int)((const long long*)ti_l)[e] : ((const int*)ti_l)[e];
            atomicAdd(&s_acc[il], 1.f);
            atomicAdd(&s_acc[16 + il], vl);
            float vg = tv_g[e];
            int ig = i64g ? (int)((const long long*)ti_g)[e] : ((const int*)ti_g)[e];
            atomicAdd(&s_acc[8 + ig], 1.f);
            atomicAdd(&s_acc[24 + ig], vg);
        }

        const float4* pl = (const float4*)(gl_l + (size_t)gid * 8);
        const float4* pg = (const float4*)(gl_g + (size_t)gid * 8);
        float ll = lse8(pl[0], pl[1]);
        float lg = lse8(pg[0], pg[1]);
        float zl = ll * ll, zg = lg * lg;
#pragma unroll
        for (int off = 16; off; off >>= 1) {
            zl += __shfl_down_sync(0xffffffffu, zl, off);
            zg += __shfl_down_sync(0xffffffffu, zg, off);
        }
        if (lane == 0) { s_z[warp][0] = zl; s_z[warp][1] = zg; }
        __syncthreads();

        if (tid == 0) {
            float a = 0.f, b = 0.f;
#pragma unroll
            for (int w = 0; w < 8; w++) { a += s_z[w][0]; b += s_z[w][1]; }
            g_bpart[mb][0] = a;
            g_bpart[mb][1] = b;
        }
        if (tid < 32) g_bpart[mb][2 + tid] = s_acc[tid];
    }

    // ---- phase 3: threadfence reduction; last block assembles the result
    __shared__ unsigned s_last;
    __threadfence();
    if (tid == 0) {
        unsigned t = atomicInc(&g_ctr, GRID - 1);   // wraps to 0 -> auto reset
        s_last = (t == GRID - 1);
    }
    __syncthreads();
    if (!s_last) return;
    __threadfence();

    {
        __shared__ float s_red[8];
        __shared__ float s_ls;
        float acc = 0.f;
#pragma unroll
        for (int i = 0; i < NROWS / 256; i++)
            acc += __ldcg(&g_row_partial[i * 256 + tid]);
#pragma unroll
        for (int off = 16; off; off >>= 1)
            acc += __shfl_down_sync(0xffffffffu, acc, off);
        if (lane == 0) s_red[warp] = acc;
        __syncthreads();

        if (tid < 32) {
            float t = (lane < 8) ? s_red[lane] : 0.f;
#pragma unroll
            for (int off = 4; off; off >>= 1)
                t += __shfl_down_sync(0xffffffffu, t, off);
            if (lane == 0) s_ls = t;

            // MoE partial reduce: 32 lanes = 32 moe blocks
            float zl = __ldcg(&g_bpart[lane][0]), zg = __ldcg(&g_bpart[lane][1]);
            float cl[8], cg[8], sl[8], sg[8];
#pragma unroll
            for (int j = 0; j < 8; j++) {
                cl[j] = __ldcg(&g_bpart[lane][2 + j]);
                cg[j] = __ldcg(&g_bpart[lane][10 + j]);
                sl[j] = __ldcg(&g_bpart[lane][18 + j]);
                sg[j] = __ldcg(&g_bpart[lane][26 + j]);
            }
#pragma unroll
            for (int off = 16; off; off >>= 1) {
                zl += __shfl_down_sync(0xffffffffu, zl, off);
                zg += __shfl_down_sync(0xffffffffu, zg, off);
#pragma unroll
                for (int j = 0; j < 8; j++) {
                    cl[j] += __shfl_down_sync(0xffffffffu, cl[j], off);
                    cg[j] += __shfl_down_sync(0xffffffffu, cg[j], off);
                    sl[j] += __shfl_down_sync(0xffffffffu, sl[j], off);
                    sg[j] += __shfl_down_sync(0xffffffffu, sg[j], off);
                }
            }
            if (lane == 0) {
                float loadl = 0.f, loadg = 0.f;
#pragma unroll
                for (int j = 0; j < 8; j++) {
                    loadl += cl[j] * sl[j];
                    loadg += cg[j] * sg[j];
                }
                // load_balance = E/num_tokens * sum(count*sum); num_tokens = 8192
                float lb = 0.01f * 0.5f * ((float)NE / (float)NROWS) * (loadl + loadg);
                float zz = 0.001f * 0.5f * ((zl + zg) / (float)NROWS);
                out[0] = s_ls / 8.0f + lb + zz;   // denom = B = 8 (NORMALIZE_LENGTH=False)
            }
        }
    }
}

// ---------------------------------------------------------------------------
// Launch. Input order: x, target, topk_values_local, topk_indices_local,
// gate_logits_local, topk_values_global, topk_indices_global,
// gate_logits_global.
// ---------------------------------------------------------------------------
extern "C" void kernel_launch(void* const* d_in, const int* in_sizes, int n_in,
                              void* d_out, int out_size)
{
    const float* x    = (const float*)d_in[0];
    const void*  tgt  = d_in[1];
    const float* tvl  = (const float*)d_in[2];
    const void*  til  = d_in[3];
    const float* gll  = (const float*)d_in[4];
    const float* tvg  = (const float*)d_in[5];
    const void*  tig  = d_in[6];
    const float* glg  = (const float*)d_in[7];

    fused_kernel<<<GRID, 256>>>(x, tgt, tvl, til, gll, tvg, tig, glg, (float*)d_out);
}

// round 12
// speedup vs baseline: 1.0233x; 1.0233x over previous
#include <cuda_runtime.h>
#include <math.h>

// Problem constants: B=8, T=1024, V=10000, N=8192, K=2, E=8
#define VDIM    10000
#define NROWS   8192
#define NE      8
#define MOEBLK  32

// Scratch (no device allocation allowed -> __device__ globals)
__device__ float    g_row_partial[NROWS];
// per-moe-block partials:
// [0]=z_local [1]=z_global [2..9]=cnt_l [10..17]=cnt_g [18..25]=sum_l [26..33]=sum_g
__device__ float    g_bpart[MOEBLK][34];
__device__ unsigned g_ctr;          // zero-init; atomicInc wraps -> replay-safe

__device__ __forceinline__ float lse8(float4 a, float4 b)
{
    float m = fmaxf(fmaxf(fmaxf(a.x, a.y), fmaxf(a.z, a.w)),
                    fmaxf(fmaxf(b.x, b.y), fmaxf(b.z, b.w)));
    float s = __expf(a.x - m) + __expf(a.y - m) + __expf(a.z - m) + __expf(a.w - m)
            + __expf(b.x - m) + __expf(b.y - m) + __expf(b.z - m) + __expf(b.w - m);
    return m + __logf(s);
}

// ---------------------------------------------------------------------------
// One launch, grid = 8192 (one row per block, the R7 streaming shape):
//   phase 1: per-row label-smoothing partial (single pass, branchless exp)
//   phase 2: blocks 0..31 also compute MoE side losses
//   phase 3: last block (threadfence reduction) assembles the scalar
// __launch_bounds__(256, 8) pins the hot loop at <=32 regs (8 blocks/SM).
// ---------------------------------------------------------------------------
__global__ __launch_bounds__(256, 8) void fused_kernel(
    const float* __restrict__ x, const void* __restrict__ target,
    const float* __restrict__ tv_l, const void* __restrict__ ti_l, const float* __restrict__ gl_l,
    const float* __restrict__ tv_g, const void* __restrict__ ti_g, const float* __restrict__ gl_g,
    float* __restrict__ out)
{
    const int tid  = threadIdx.x;
    const int lane = tid & 31, warp = tid >> 5;
    const int row  = blockIdx.x;
    const float* xr = x + (size_t)row * VDIM;
    const float4* x4 = (const float4*)xr;

    // ---- phase 1: one row per block, single streaming pass
    float s0 = 0.f, s1 = 0.f, s2 = 0.f, s3 = 0.f;
    float a0 = 0.f, a1 = 0.f, a2 = 0.f, a3 = 0.f;

    // 2500 float4 per row = 9 full strides of 256 + tail of 196
#pragma unroll
    for (int it = 0; it < 9; it++) {
        float4 v = x4[it * 256 + tid];
        a0 += v.x; a1 += v.y; a2 += v.z; a3 += v.w;
        s0 += __expf(v.x); s1 += __expf(v.y);
        s2 += __expf(v.z); s3 += __expf(v.w);
    }
    if (tid < 196) {
        float4 v = x4[2304 + tid];
        a0 += v.x; a1 += v.y; a2 += v.z; a3 += v.w;
        s0 += __expf(v.x); s1 += __expf(v.y);
        s2 += __expf(v.z); s3 += __expf(v.w);
    }

    float s  = (s0 + s1) + (s2 + s3);
    float sx = (a0 + a1) + (a2 + a3);
#pragma unroll
    for (int off = 16; off; off >>= 1) {
        s  += __shfl_down_sync(0xffffffffu, s,  off);
        sx += __shfl_down_sync(0xffffffffu, sx, off);
    }

    __shared__ float shs[8], shx[8];
    if (lane == 0) { shs[warp] = s; shx[warp] = sx; }
    __syncthreads();

    if (tid < 32) {
        s  = (lane < 8) ? shs[lane] : 0.f;
        sx = (lane < 8) ? shx[lane] : 0.f;
#pragma unroll
        for (int off = 4; off; off >>= 1) {
            s  += __shfl_down_sync(0xffffffffu, s,  off);
            sx += __shfl_down_sync(0xffffffffu, sx, off);
        }
        // dtype detection for target: int64 non-negative small values viewed
        // as u32 have ALL odd words zero; int32 targets in [0,10000) never do.
        unsigned tw = ((const unsigned*)target)[1 + 2 * lane];
        unsigned nz = __ballot_sync(0xffffffffu, tw != 0u);
        if (lane == 0) {
            float lse = __logf(s);
            long long tgt = (nz == 0u) ? ((const long long*)target)[row]
                                       : (long long)((const int*)target)[row];
            float kl = 0.f;
            if (tgt >= 0) {
                const float SM  = 0.1f / (float)(VDIM - 1);
                const float ENT = -1.2461070101f;  // 0.1*log(0.1/9999)+0.9*log(0.9)
                float xt = __ldg(xr + tgt);
                float sum_logp = sx - (float)VDIM * lse;
                float logp_tgt = xt - lse;
                float cross = SM * sum_logp + (0.9f - SM) * logp_tgt;
                kl = ENT - cross;
            }
            g_row_partial[row] = kl;
        }
    }

    // ---- phase 2: MoE side losses in blocks 0..31 (wave-1, off tail path)
    if (blockIdx.x < MOEBLK) {
        const int mb = blockIdx.x;

        __shared__ float s_acc[32];  // [0..7]=cnt_l [8..15]=cnt_g [16..23]=sum_l [24..31]=sum_g
        __shared__ float s_z[8][2];
        __shared__ int   s_is64[2];

        if (tid < 32) {
            s_acc[tid] = 0.f;
            unsigned wl = ((const unsigned*)ti_l)[1 + 2 * tid];
            unsigned wg = ((const unsigned*)ti_g)[1 + 2 * tid];
            unsigned bl = __ballot_sync(0xffffffffu, wl != 0u);
            unsigned bg = __ballot_sync(0xffffffffu, wg != 0u);
            if (tid == 0) { s_is64[0] = (bl == 0u); s_is64[1] = (bg == 0u); }
        }
        __syncthreads();

        const int gid = mb * 256 + tid;          // 0..8191
        const int i64l = s_is64[0], i64g = s_is64[1];

#pragma unroll
        for (int rep = 0; rep < 2; rep++) {
            int e = gid + rep * NROWS;           // flattened (N,K) row-major
            float vl = tv_l[e];
            int il = i64l ? (int)((const long long*)ti_l)[e] : ((const int*)ti_l)[e];
            atomicAdd(&s_acc[il], 1.f);
            atomicAdd(&s_acc[16 + il], vl);
            float vg = tv_g[e];
            int ig = i64g ? (int)((const long long*)ti_g)[e] : ((const int*)ti_g)[e];
            atomicAdd(&s_acc[8 + ig], 1.f);
            atomicAdd(&s_acc[24 + ig], vg);
        }

        const float4* pl = (const float4*)(gl_l + (size_t)gid * 8);
        const float4* pg = (const float4*)(gl_g + (size_t)gid * 8);
        float ll = lse8(pl[0], pl[1]);
        float lg = lse8(pg[0], pg[1]);
        float zl = ll * ll, zg = lg * lg;
#pragma unroll
        for (int off = 16; off; off >>= 1) {
            zl += __shfl_down_sync(0xffffffffu, zl, off);
            zg += __shfl_down_sync(0xffffffffu, zg, off);
        }
        if (lane == 0) { s_z[warp][0] = zl; s_z[warp][1] = zg; }
        __syncthreads();

        if (tid == 0) {
            float a = 0.f, b = 0.f;
#pragma unroll
            for (int w = 0; w < 8; w++) { a += s_z[w][0]; b += s_z[w][1]; }
            g_bpart[mb][0] = a;
            g_bpart[mb][1] = b;
        }
        if (tid < 32) g_bpart[mb][2 + tid] = s_acc[tid];
    }

    // ---- phase 3: threadfence reduction; last-arriving block assembles
    __shared__ unsigned s_last;
    __threadfence();
    if (tid == 0) {
        unsigned t = atomicInc(&g_ctr, NROWS - 1);   // wraps to 0 -> auto reset
        s_last = (t == NROWS - 1);
    }
    __syncthreads();
    if (!s_last) return;
    __threadfence();

    {
        __shared__ float s_red[8];
        __shared__ float s_ls;
        float acc = 0.f;
#pragma unroll
        for (int i = 0; i < NROWS / 256; i++)
            acc += __ldcg(&g_row_partial[i * 256 + tid]);
#pragma unroll
        for (int off = 16; off; off >>= 1)
            acc += __shfl_down_sync(0xffffffffu, acc, off);
        if (lane == 0) s_red[warp] = acc;
        __syncthreads();

        if (tid < 32) {
            float t = (lane < 8) ? s_red[lane] : 0.f;
#pragma unroll
            for (int off = 4; off; off >>= 1)
                t += __shfl_down_sync(0xffffffffu, t, off);
            if (lane == 0) s_ls = t;

            // MoE partial reduce: 32 lanes = 32 moe blocks
            float zl = __ldcg(&g_bpart[lane][0]), zg = __ldcg(&g_bpart[lane][1]);
            float cl[8], cg[8], sl[8], sg[8];
#pragma unroll
            for (int j = 0; j < 8; j++) {
                cl[j] = __ldcg(&g_bpart[lane][2 + j]);
                cg[j] = __ldcg(&g_bpart[lane][10 + j]);
                sl[j] = __ldcg(&g_bpart[lane][18 + j]);
                sg[j] = __ldcg(&g_bpart[lane][26 + j]);
            }
#pragma unroll
            for (int off = 16; off; off >>= 1) {
                zl += __shfl_down_sync(0xffffffffu, zl, off);
                zg += __shfl_down_sync(0xffffffffu, zg, off);
#pragma unroll
                for (int j = 0; j < 8; j++) {
                    cl[j] += __shfl_down_sync(0xffffffffu, cl[j], off);
                    cg[j] += __shfl_down_sync(0xffffffffu, cg[j], off);
                    sl[j] += __shfl_down_sync(0xffffffffu, sl[j], off);
                    sg[j] += __shfl_down_sync(0xffffffffu, sg[j], off);
                }
            }
            if (lane == 0) {
                float loadl = 0.f, loadg = 0.f;
#pragma unroll
                for (int j = 0; j < 8; j++) {
                    loadl += cl[j] * sl[j];
                    loadg += cg[j] * sg[j];
                }
                // load_balance = E/num_tokens * sum(count*sum); num_tokens = 8192
                float lb = 0.01f * 0.5f * ((float)NE / (float)NROWS) * (loadl + loadg);
                float zz = 0.001f * 0.5f * ((zl + zg) / (float)NROWS);
                out[0] = s_ls / 8.0f + lb + zz;   // denom = B = 8 (NORMALIZE_LENGTH=False)
            }
        }
    }
}

// ---------------------------------------------------------------------------
// Launch. Input order: x, target, topk_values_local, topk_indices_local,
// gate_logits_local, topk_values_global, topk_indices_global,
// gate_logits_global.
// ---------------------------------------------------------------------------
extern "C" void kernel_launch(void* const* d_in, const int* in_sizes, int n_in,
                              void* d_out, int out_size)
{
    const float* x    = (const float*)d_in[0];
    const void*  tgt  = d_in[1];
    const float* tvl  = (const float*)d_in[2];
    const void*  til  = d_in[3];
    const float* gll  = (const float*)d_in[4];
    const float* tvg  = (const float*)d_in[5];
    const void*  tig  = d_in[6];
    const float* glg  = (const float*)d_in[7];

    fused_kernel<<<NROWS, 256>>>(x, tgt, tvl, til, gll, tvg, tig, glg, (float*)d_out);
}

// round 13
// speedup vs baseline: 1.1708x; 1.1442x over previous
#include <cuda_runtime.h>
#include <math.h>

// Problem constants: B=8, T=1024, V=10000, N=8192, K=2, E=8
#define VDIM    10000
#define NROWS   8192
#define NE      8
#define MOEBLK  32
#define KLSCALE 67108864.0f     // 2^26 fixed-point scale for the kl sum

// Scratch (no device allocation allowed -> __device__ globals)
// [0]=z_local [1]=z_global [2..9]=cnt_l [10..17]=cnt_g [18..25]=sum_l [26..33]=sum_g
__device__ float              g_bpart[MOEBLK][34];
__device__ unsigned long long g_kl;   // Q26 fixed-point ls sum; reset by atomicExch
__device__ unsigned           g_ctr;  // zero-init; atomicInc wraps -> replay-safe

__device__ __forceinline__ float lse8(float4 a, float4 b)
{
    float m = fmaxf(fmaxf(fmaxf(a.x, a.y), fmaxf(a.z, a.w)),
                    fmaxf(fmaxf(b.x, b.y), fmaxf(b.z, b.w)));
    float s = __expf(a.x - m) + __expf(a.y - m) + __expf(a.z - m) + __expf(a.w - m)
            + __expf(b.x - m) + __expf(b.y - m) + __expf(b.z - m) + __expf(b.w - m);
    return m + __logf(s);
}

// ---------------------------------------------------------------------------
// One launch, grid = 8192 (one row per block, R7 streaming shape):
//   phase 1: per-row label-smoothing partial; lane0 fires a fire-and-forget
//            fixed-point atomicAdd (REDG, no wait)
//   phase 2: blocks 0..31 also compute MoE side losses (wave-1, overlapped)
//   phase 3: warps 1-7 exit; warp 0 does fence + atomicInc; last block
//            assembles the scalar (atomicExch reads+resets the kl sum)
// ---------------------------------------------------------------------------
__global__ __launch_bounds__(256, 8) void fused_kernel(
    const float* __restrict__ x, const void* __restrict__ target,
    const float* __restrict__ tv_l, const void* __restrict__ ti_l, const float* __restrict__ gl_l,
    const float* __restrict__ tv_g, const void* __restrict__ ti_g, const float* __restrict__ gl_g,
    float* __restrict__ out)
{
    const int tid  = threadIdx.x;
    const int lane = tid & 31, warp = tid >> 5;
    const int row  = blockIdx.x;
    const float* xr = x + (size_t)row * VDIM;
    const float4* x4 = (const float4*)xr;

    // ---- phase 1: one row per block, single streaming pass
    float s0 = 0.f, s1 = 0.f, s2 = 0.f, s3 = 0.f;
    float a0 = 0.f, a1 = 0.f, a2 = 0.f, a3 = 0.f;

    // 2500 float4 per row = 9 full strides of 256 + tail of 196
#pragma unroll
    for (int it = 0; it < 9; it++) {
        float4 v = x4[it * 256 + tid];
        a0 += v.x; a1 += v.y; a2 += v.z; a3 += v.w;
        s0 += __expf(v.x); s1 += __expf(v.y);
        s2 += __expf(v.z); s3 += __expf(v.w);
    }
    if (tid < 196) {
        float4 v = x4[2304 + tid];
        a0 += v.x; a1 += v.y; a2 += v.z; a3 += v.w;
        s0 += __expf(v.x); s1 += __expf(v.y);
        s2 += __expf(v.z); s3 += __expf(v.w);
    }

    float s  = (s0 + s1) + (s2 + s3);
    float sx = (a0 + a1) + (a2 + a3);
#pragma unroll
    for (int off = 16; off; off >>= 1) {
        s  += __shfl_down_sync(0xffffffffu, s,  off);
        sx += __shfl_down_sync(0xffffffffu, sx, off);
    }

    __shared__ float shs[8], shx[8];
    if (lane == 0) { shs[warp] = s; shx[warp] = sx; }
    __syncthreads();

    if (tid < 32) {
        s  = (lane < 8) ? shs[lane] : 0.f;
        sx = (lane < 8) ? shx[lane] : 0.f;
#pragma unroll
        for (int off = 4; off; off >>= 1) {
            s  += __shfl_down_sync(0xffffffffu, s,  off);
            sx += __shfl_down_sync(0xffffffffu, sx, off);
        }
        // dtype detection for target: int64 non-negative small values viewed
        // as u32 have ALL odd words zero; int32 targets in [0,10000) never do.
        unsigned tw = ((const unsigned*)target)[1 + 2 * lane];
        unsigned nz = __ballot_sync(0xffffffffu, tw != 0u);
        if (lane == 0) {
            float lse = __logf(s);
            long long tgt = (nz == 0u) ? ((const long long*)target)[row]
                                       : (long long)((const int*)target)[row];
            float kl = 0.f;
            if (tgt >= 0) {
                const float SM  = 0.1f / (float)(VDIM - 1);
                const float ENT = -1.2461070101f;  // 0.1*log(0.1/9999)+0.9*log(0.9)
                float xt = __ldg(xr + tgt);
                float sum_logp = sx - (float)VDIM * lse;
                float logp_tgt = xt - lse;
                float cross = SM * sum_logp + (0.9f - SM) * logp_tgt;
                kl = ENT - cross;
            }
            // fire-and-forget fixed-point add (REDG: return unused, no wait);
            // integer adds commute exactly -> deterministic across replays
            long long fx = llrintf(kl * KLSCALE);
            atomicAdd(&g_kl, (unsigned long long)fx);
        }
    }

    // ---- phase 2: MoE side losses in blocks 0..31 (wave-1, overlapped)
    if (blockIdx.x < MOEBLK) {
        const int mb = blockIdx.x;

        __shared__ float s_acc[32];  // [0..7]=cnt_l [8..15]=cnt_g [16..23]=sum_l [24..31]=sum_g
        __shared__ float s_z[8][2];
        __shared__ int   s_is64[2];

        if (tid < 32) {
            s_acc[tid] = 0.f;
            unsigned wl = ((const unsigned*)ti_l)[1 + 2 * tid];
            unsigned wg = ((const unsigned*)ti_g)[1 + 2 * tid];
            unsigned bl = __ballot_sync(0xffffffffu, wl != 0u);
            unsigned bg = __ballot_sync(0xffffffffu, wg != 0u);
            if (tid == 0) { s_is64[0] = (bl == 0u); s_is64[1] = (bg == 0u); }
        }
        __syncthreads();

        const int gid = mb * 256 + tid;          // 0..8191
        const int i64l = s_is64[0], i64g = s_is64[1];

#pragma unroll
        for (int rep = 0; rep < 2; rep++) {
            int e = gid + rep * NROWS;           // flattened (N,K) row-major
            float vl = tv_l[e];
            int il = i64l ? (int)((const long long*)ti_l)[e] : ((const int*)ti_l)[e];
            atomicAdd(&s_acc[il], 1.f);
            atomicAdd(&s_acc[16 + il], vl);
            float vg = tv_g[e];
            int ig = i64g ? (int)((const long long*)ti_g)[e] : ((const int*)ti_g)[e];
            atomicAdd(&s_acc[8 + ig], 1.f);
            atomicAdd(&s_acc[24 + ig], vg);
        }

        const float4* pl = (const float4*)(gl_l + (size_t)gid * 8);
        const float4* pg = (const float4*)(gl_g + (size_t)gid * 8);
        float ll = lse8(pl[0], pl[1]);
        float lg = lse8(pg[0], pg[1]);
        float zl = ll * ll, zg = lg * lg;
#pragma unroll
        for (int off = 16; off; off >>= 1) {
            zl += __shfl_down_sync(0xffffffffu, zl, off);
            zg += __shfl_down_sync(0xffffffffu, zg, off);
        }
        if (lane == 0) { s_z[warp][0] = zl; s_z[warp][1] = zg; }
        __syncthreads();

        if (tid == 0) {
            float a = 0.f, b = 0.f;
#pragma unroll
            for (int w = 0; w < 8; w++) { a += s_z[w][0]; b += s_z[w][1]; }
            g_bpart[mb][0] = a;
            g_bpart[mb][1] = b;
        }
        if (tid < 32) g_bpart[mb][2 + tid] = s_acc[tid];
    }

    // ---- phase 3: warps 1-7 are done; warp 0 handles completion
    if (warp != 0) return;

    __threadfence();                              // publish kl add + g_bpart
    unsigned t = 0;
    if (lane == 0) t = atomicInc(&g_ctr, NROWS - 1);   // wraps -> replay-safe
    t = __shfl_sync(0xffffffffu, t, 0);
    if (t != NROWS - 1) return;                   // not the last block
    __threadfence();                              // acquire all published data

    // last block, warp 0: assemble the scalar
    {
        unsigned long long raw = 0ull;
        if (lane == 0) raw = atomicExch(&g_kl, 0ull);   // read + reset in one op
        float ls_sum = 0.f;
        if (lane == 0) ls_sum = (float)((long long)raw) * (1.0f / KLSCALE);

        // MoE partial reduce: 32 lanes = 32 moe blocks
        float zl = __ldcg(&g_bpart[lane][0]), zg = __ldcg(&g_bpart[lane][1]);
        float cl[8], cg[8], sl[8], sg[8];
#pragma unroll
        for (int j = 0; j < 8; j++) {
            cl[j] = __ldcg(&g_bpart[lane][2 + j]);
            cg[j] = __ldcg(&g_bpart[lane][10 + j]);
            sl[j] = __ldcg(&g_bpart[lane][18 + j]);
            sg[j] = __ldcg(&g_bpart[lane][26 + j]);
        }
#pragma unroll
        for (int off = 16; off; off >>= 1) {
            zl += __shfl_down_sync(0xffffffffu, zl, off);
            zg += __shfl_down_sync(0xffffffffu, zg, off);
#pragma unroll
            for (int j = 0; j < 8; j++) {
                cl[j] += __shfl_down_sync(0xffffffffu, cl[j], off);
                cg[j] += __shfl_down_sync(0xffffffffu, cg[j], off);
                sl[j] += __shfl_down_sync(0xffffffffu, sl[j], off);
                sg[j] += __shfl_down_sync(0xffffffffu, sg[j], off);
            }
        }
        if (lane == 0) {
            float loadl = 0.f, loadg = 0.f;
#pragma unroll
            for (int j = 0; j < 8; j++) {
                loadl += cl[j] * sl[j];
                loadg += cg[j] * sg[j];
            }
            // load_balance = E/num_tokens * sum(count*sum); num_tokens = 8192
            float lb = 0.01f * 0.5f * ((float)NE / (float)NROWS) * (loadl + loadg);
            float zz = 0.001f * 0.5f * ((zl + zg) / (float)NROWS);
            out[0] = ls_sum / 8.0f + lb + zz;   // denom = B = 8 (NORMALIZE_LENGTH=False)
        }
    }
}

// ---------------------------------------------------------------------------
// Launch. Input order: x, target, topk_values_local, topk_indices_local,
// gate_logits_local, topk_values_global, topk_indices_global,
// gate_logits_global.
// ---------------------------------------------------------------------------
extern "C" void kernel_launch(void* const* d_in, const int* in_sizes, int n_in,
                              void* d_out, int out_size)
{
    const float* x    = (const float*)d_in[0];
    const void*  tgt  = d_in[1];
    const float* tvl  = (const float*)d_in[2];
    const void*  til  = d_in[3];
    const float* gll  = (const float*)d_in[4];
    const float* tvg  = (const float*)d_in[5];
    const void*  tig  = d_in[6];
    const float* glg  = (const float*)d_in[7];

    fused_kernel<<<NROWS, 256>>>(x, tgt, tvl, til, gll, tvg, tig, glg, (float*)d_out);
}